// round 12
// baseline (speedup 1.0000x reference)
#include <cuda_runtime.h>
#include <cuda_bf16.h>
#include <math.h>

#define RR 2048
#define NALLY 15
#define OD 256
#define FD 10
#define KK 650
#define KPAD 704
#define NCHUNK 11
#define ASTR 144

typedef unsigned int u32;
typedef __nv_bfloat16 bf16;

__device__ float g_EmbEn[RR*OD];
__device__ float g_EmbAlSum[RR*OD];
__device__ float g_Pd[RR*NALLY*3];
__device__ bf16 g_Ihi[3*KPAD*OD], g_Ilo[3*KPAD*OD];   // plain images (intermediate)
__device__ u32  g_Bfhi[3*90112],  g_Bflo[3*90112];    // mma B fragments (44 ks x 32 nt x 32 lane x 2 words)
__device__ bf16 g_Ahi[2*RR*KPAD], g_Alo[2*RR*KPAD];   // row-summed A images (enemy, ally)

__device__ __forceinline__ u32 smem_u32(const void* p) {
    u32 a; asm("{ .reg .u64 t; cvta.to.shared.u64 t, %1; cvt.u32.u64 %0, t; }" : "=r"(a) : "l"(p)); return a;
}
__device__ __forceinline__ void ldmA(u32* r, u32 addr) {
    asm volatile("ldmatrix.sync.aligned.m8n8.x4.shared.b16 {%0,%1,%2,%3}, [%4];"
        : "=r"(r[0]), "=r"(r[1]), "=r"(r[2]), "=r"(r[3]) : "r"(addr));
}
__device__ __forceinline__ void mma16816(float* d, const u32* a, const u32* b) {
    asm volatile("mma.sync.aligned.m16n8k16.row.col.f32.bf16.bf16.f32 "
        "{%0,%1,%2,%3},{%4,%5,%6,%7},{%8,%9},{%0,%1,%2,%3};"
        : "+f"(d[0]), "+f"(d[1]), "+f"(d[2]), "+f"(d[3])
        : "r"(a[0]), "r"(a[1]), "r"(a[2]), "r"(a[3]), "r"(b[0]), "r"(b[1]));
}

// ---------------------------------------------------------------------------
// Weight images: m=0 W2p(ally,pw1-folded), m=1 W2full_enemy, m=2 W2full_ally
__global__ void __launch_bounds__(256) wgen_kernel(
    const float* __restrict__ he_w2, const float* __restrict__ he_b2,
    const float* __restrict__ ha_w2, const float* __restrict__ ha_b2,
    const float* __restrict__ pw1) {
    __shared__ float wrow[256];
    const int m = blockIdx.x / KPAD, kk = blockIdx.x % KPAD, o = threadIdx.x;
    float v = 0.f;
    if (m == 0) {
        if (kk < KK)
            wrow[o] = (kk < 640) ? ha_w2[(kk/10)*2560 + (kk%10)*256 + o] : ha_b2[(kk-640)*256 + o];
        __syncthreads();
        if (kk < KK) {
            int hd = o >> 6, j = o & 63;
            float s = 0.f;
#pragma unroll
            for (int h = 0; h < 64; h++) s = fmaf(wrow[hd*64 + h], __ldg(pw1 + h*64 + j), s);
            v = s;
        }
    } else if (m == 1) {
        if (kk < 640) v = he_w2[(kk/10)*2820 + (kk%10)*256 + o];
        else if (kk < KK) v = he_b2[(kk-640)*256 + o];
    } else {
        if (kk < 640) v = ha_w2[(kk/10)*2560 + (kk%10)*256 + o];
        else if (kk < KK) v = ha_b2[(kk-640)*256 + o];
    }
    bf16 hi = __float2bfloat16(v);
    bf16 lo = __float2bfloat16(v - __bfloat162float(hi));
    g_Ihi[(size_t)(m*KPAD + kk)*256 + o] = hi;
    g_Ilo[(size_t)(m*KPAD + kk)*256 + o] = lo;
}

// Repack images into mma B fragments. word: low 16 = lower k.
__global__ void __launch_bounds__(256) repack_kernel() {
    const int idx = blockIdx.x*256 + threadIdx.x;   // 270336 total
    const int mat = idx / 90112, rem = idx % 90112;
    const int ks = rem / 2048, r2 = rem % 2048;
    const int nt = r2 >> 6, l = (r2 >> 1) & 31, wd = r2 & 1;
    const int k = ks*16 + (l & 3)*2 + wd*8;
    const int n = nt*8 + (l >> 2);
    const size_t p = (size_t)(mat*KPAD + k)*256 + n;
    g_Bfhi[idx] = ((u32)__bfloat16_as_ushort(g_Ihi[p + 256]) << 16) | __bfloat16_as_ushort(g_Ihi[p]);
    g_Bflo[idx] = ((u32)__bfloat16_as_ushort(g_Ilo[p + 256]) << 16) | __bfloat16_as_ushort(g_Ilo[p]);
}

// ---------------------------------------------------------------------------
// Build row-summed A images (split bf16). bid<128 enemy, else ally.
__global__ void __launch_bounds__(128) asum_kernel(
    const float* __restrict__ enemy, const float* __restrict__ ally,
    const float* __restrict__ eW1, const float* __restrict__ eB1,
    const float* __restrict__ aW1, const float* __restrict__ aB1) {
    __shared__ float a_sh[KK*16];
    __shared__ float e_sh[16*161];
    const int tid = threadIdx.x;
    const bool EN = blockIdx.x < 128;
    const int ag0 = (EN ? blockIdx.x : blockIdx.x - 128) * 16;
    const float* feats = EN ? enemy : ally;
    const float* W1 = EN ? eW1 : aW1;
    const float* B1 = EN ? eB1 : aB1;
    const int per = EN ? 160 : 150;

    for (int idx = tid; idx < 16*160; idx += 128) {
        int a = idx / 160, rem = idx - a*160;
        e_sh[a*161 + rem] = (rem < per) ? feats[(size_t)(ag0 + a)*per + rem] : 0.f;
    }
    __syncthreads();
#pragma unroll
    for (int p = 0; p < 8; p++) {
        int idx = tid + p*128;
        int a = idx & 15, k = idx >> 4;
        const float* ea = e_sh + a*161;
        float h[16];
#pragma unroll
        for (int rr = 0; rr < 16; rr++) {
            float s = B1[k];
#pragma unroll
            for (int i = 0; i < FD; i++) s = fmaf(ea[rr*FD + i], __ldg(W1 + i*64 + k), s);
            h[rr] = fmaxf(s, 0.f);   // padded rows: e=0 kills contribution below
        }
#pragma unroll
        for (int i = 0; i < FD; i++) {
            float s = 0.f;
#pragma unroll
            for (int rr = 0; rr < 16; rr++) s = fmaf(h[rr], ea[rr*FD + i], s);
            a_sh[(k*10 + i)*16 + a] = s;
        }
    }
    for (int idx = tid; idx < 160; idx += 128) {
        int a = idx & 15, i = idx >> 4;
        const float* ea = e_sh + a*161;
        float s = 0.f;
#pragma unroll
        for (int rr = 0; rr < 16; rr++) s += ea[rr*FD + i];
        a_sh[(640 + i)*16 + a] = s;
    }
    __syncthreads();
    const size_t rbase = (size_t)((EN ? 0 : RR) + ag0);
    for (int idx = tid; idx < 16*KPAD; idx += 128) {
        int a = idx / KPAD, kk = idx - a*KPAD;
        float v = (kk < KK) ? a_sh[kk*16 + a] : 0.f;
        bf16 hi = __float2bfloat16(v);
        bf16 lo = __float2bfloat16(v - __bfloat162float(hi));
        g_Ahi[(rbase + a)*KPAD + kk] = hi;
        g_Alo[(rbase + a)*KPAD + kk] = lo;
    }
}

// ---------------------------------------------------------------------------
// Shared MMA core: one K chunk (64), A in smem (hi/lo, ASTR rows), B frags gmem.
// Pass-major mma order to stretch accumulator reuse distance.
__device__ __forceinline__ void mma_chunk(u32 saHi, u32 saLo,
        const uint2* __restrict__ bfh, const uint2* __restrict__ bfl,
        int c, int w, int l, float d[4][4][4]) {
    const u32 aRow = (u32)((l & 15)*ASTR + (l >> 4)*16);
#pragma unroll
    for (int kt = 0; kt < 4; kt++) {
        u32 ah[4][4], al_[4][4];
#pragma unroll
        for (int mt = 0; mt < 4; mt++) {
            u32 ab = (u32)(mt*16*ASTR + kt*32) + aRow;
            ldmA(ah[mt],  saHi + ab);
            ldmA(al_[mt], saLo + ab);
        }
        const size_t fb = ((size_t)(c*4 + kt)*32 + w*4)*32 + l;
#pragma unroll
        for (int nt = 0; nt < 4; nt++) {
            uint2 bhv2 = __ldg(bfh + fb + nt*32);
            uint2 blv2 = __ldg(bfl + fb + nt*32);
            u32 bh[2] = {bhv2.x, bhv2.y}, bl[2] = {blv2.x, blv2.y};
#pragma unroll
            for (int mt = 0; mt < 4; mt++) mma16816(d[mt][nt], ah[mt],  bh);
#pragma unroll
            for (int mt = 0; mt < 4; mt++) mma16816(d[mt][nt], ah[mt],  bl);
#pragma unroll
            for (int mt = 0; mt < 4; mt++) mma16816(d[mt][nt], al_[mt], bh);
        }
    }
}

// ---------------------------------------------------------------------------
// Summed GEMM: 64 blocks (32 enemy + 32 ally), 64 rows each, N=256.
__global__ void __launch_bounds__(256) gemm_sum_kernel() {
    __shared__ __align__(16) char smA[2*9216];
    const int tid = threadIdx.x, w = tid >> 5, l = tid & 31;
    const bool EN = blockIdx.x < 32;
    const int rowbase = (EN ? blockIdx.x : blockIdx.x - 32) * 64;
    const bf16* Ah = g_Ahi + (EN ? 0 : (size_t)RR*KPAD);
    const bf16* Al = g_Alo + (EN ? 0 : (size_t)RR*KPAD);
    const int mat = EN ? 1 : 2;
    const uint2* bfh = (const uint2*)g_Bfhi + (size_t)mat*45056;
    const uint2* bfl = (const uint2*)g_Bflo + (size_t)mat*45056;
    const u32 sb = smem_u32(smA);

    float d[4][4][4];
#pragma unroll
    for (int a = 0; a < 4; a++)
#pragma unroll
        for (int b = 0; b < 4; b++)
#pragma unroll
            for (int q = 0; q < 4; q++) d[a][b][q] = 0.f;

    for (int c = 0; c < NCHUNK; c++) {
        __syncthreads();
        for (int s = tid; s < 512; s += 256) {
            int r = s >> 3, q = s & 7;
            *(uint4*)(smA + r*ASTR + q*16)        = *(const uint4*)(Ah + (size_t)(rowbase + r)*KPAD + c*64 + q*8);
            *(uint4*)(smA + 9216 + r*ASTR + q*16) = *(const uint4*)(Al + (size_t)(rowbase + r)*KPAD + c*64 + q*8);
        }
        __syncthreads();
        mma_chunk(sb, sb + 9216, bfh, bfl, c, w, l, d);
    }
    float* outp = EN ? g_EmbEn : g_EmbAlSum;
#pragma unroll
    for (int mt = 0; mt < 4; mt++)
#pragma unroll
        for (int nt = 0; nt < 4; nt++)
#pragma unroll
            for (int q = 0; q < 4; q++) {
                int row = rowbase + mt*16 + (l >> 2) + (q >> 1)*8;
                int col = (w*4 + nt)*8 + (l & 3)*2 + (q & 1);
                outp[(size_t)row*OD + col] = d[mt][nt][q];
            }
}

// ---------------------------------------------------------------------------
// Ally layer-1 GEMM (A built in-kernel) + fused relu/pw2/head-mean epilogue.
#define SA_HI 0
#define SA_LO 9216
#define SE    18432
#define SH    20992
#define SW1   23040
#define SB1   25600
#define SPWE  25856
#define SPD   26880
__global__ void __launch_bounds__(256) ally_mma_kernel(
    const float* __restrict__ feats, const float* __restrict__ W1, const float* __restrict__ B1,
    const float* __restrict__ pb1, const float* __restrict__ pw2, const float* __restrict__ pb2)
{
    __shared__ __align__(16) char smem[33024];
    const int tid = threadIdx.x, w = tid >> 5, l = tid & 31;
    const u32 sb = smem_u32(smem);
    const int base = blockIdx.x * 64;

    float* e_sh  = (float*)(smem + SE);
    float* h_sh  = (float*)(smem + SH);
    float* w1_sh = (float*)(smem + SW1);
    float* b1_sh = (float*)(smem + SB1);
    float* pwe   = (float*)(smem + SPWE);
    float* pd_sh = (float*)(smem + SPD);

    for (int idx = tid; idx < 640; idx += 256) {
        int m = idx / 10, i = idx - m*10;
        e_sh[i*64 + m] = __ldg(feats + (size_t)base*FD + idx);
        w1_sh[idx] = __ldg(W1 + idx);
    }
    if (tid < 64) b1_sh[tid] = B1[tid];
    pwe[tid] = (tid < 64) ? __ldg(pb1 + tid) : __ldg(pw2 + tid - 64);
    __syncthreads();

    const uint2* bfh = (const uint2*)g_Bfhi;   // mat 0 = W2p
    const uint2* bfl = (const uint2*)g_Bflo;

    float d[4][4][4];
#pragma unroll
    for (int a = 0; a < 4; a++)
#pragma unroll
        for (int b = 0; b < 4; b++)
#pragma unroll
            for (int q = 0; q < 4; q++) d[a][b][q] = 0.f;

    const int m64 = tid & 63, part = tid >> 6;

    for (int c = 0; c < NCHUNK; c++) {
        __syncthreads();
        const int k0 = (c*64) / 10;
        const int kcnt = (c < 10) ? ((c*64 + 63)/10 - k0 + 1) : 0;
        for (int idx = tid; idx < kcnt*64; idx += 256) {
            int kr = idx >> 6, mm = idx & 63;
            float s = b1_sh[k0 + kr];
#pragma unroll
            for (int i = 0; i < FD; i++) s = fmaf(e_sh[i*64 + mm], w1_sh[i*64 + k0 + kr], s);
            h_sh[kr*64 + mm] = fmaxf(s, 0.f);
        }
        if (kcnt) __syncthreads();

        {   // A build: row m64, 16 k-lanes per thread (hi+lo)
            u32 hi[8], lo[8];
#pragma unroll
            for (int u = 0; u < 8; u++) {
                float x[2];
#pragma unroll
                for (int v2 = 0; v2 < 2; v2++) {
                    int kk = c*64 + part*16 + 2*u + v2;
                    float xv;
                    if (kk < 640) {
                        int k = (kk*6554) >> 16, i = kk - k*10;
                        xv = h_sh[(k - k0)*64 + m64] * e_sh[i*64 + m64];
                    } else if (kk < KK) xv = e_sh[(kk - 640)*64 + m64];
                    else xv = 0.f;
                    x[v2] = xv;
                }
                bf16 h0 = __float2bfloat16(x[0]), h1 = __float2bfloat16(x[1]);
                bf16 g0 = __float2bfloat16(x[0] - __bfloat162float(h0));
                bf16 g1 = __float2bfloat16(x[1] - __bfloat162float(h1));
                hi[u] = ((u32)__bfloat16_as_ushort(h1) << 16) | __bfloat16_as_ushort(h0);
                lo[u] = ((u32)__bfloat16_as_ushort(g1) << 16) | __bfloat16_as_ushort(g0);
            }
            int off = m64*ASTR + part*32;
            *(uint4*)(smem + SA_HI + off)      = make_uint4(hi[0], hi[1], hi[2], hi[3]);
            *(uint4*)(smem + SA_HI + off + 16) = make_uint4(hi[4], hi[5], hi[6], hi[7]);
            *(uint4*)(smem + SA_LO + off)      = make_uint4(lo[0], lo[1], lo[2], lo[3]);
            *(uint4*)(smem + SA_LO + off + 16) = make_uint4(lo[4], lo[5], lo[6], lo[7]);
        }
        __syncthreads();
        mma_chunk(sb + SA_HI, sb + SA_LO, bfh, bfl, c, w, l, d);
    }

    // Epilogue: t=relu(z+pb1); pd += t*pw2; quad-shuffle + smem reduce
    float pdl[4][2][3];
#pragma unroll
    for (int mt = 0; mt < 4; mt++)
#pragma unroll
        for (int h = 0; h < 2; h++)
#pragma unroll
            for (int cc = 0; cc < 3; cc++) pdl[mt][h][cc] = 0.f;
#pragma unroll
    for (int mt = 0; mt < 4; mt++)
#pragma unroll
        for (int nt = 0; nt < 4; nt++) {
            int colA = (w*4 + nt)*8 + (l & 3)*2;
            int jA = colA & 63, jB = (colA + 1) & 63;
#pragma unroll
            for (int h = 0; h < 2; h++) {
                float t0 = fmaxf(d[mt][nt][2*h    ] + pwe[jA], 0.f);
                float t1 = fmaxf(d[mt][nt][2*h + 1] + pwe[jB], 0.f);
#pragma unroll
                for (int cc = 0; cc < 3; cc++) {
                    pdl[mt][h][cc] = fmaf(t0, pwe[64 + jA*3 + cc], pdl[mt][h][cc]);
                    pdl[mt][h][cc] = fmaf(t1, pwe[64 + jB*3 + cc], pdl[mt][h][cc]);
                }
            }
        }
#pragma unroll
    for (int mt = 0; mt < 4; mt++)
#pragma unroll
        for (int h = 0; h < 2; h++)
#pragma unroll
            for (int cc = 0; cc < 3; cc++) {
                float v = pdl[mt][h][cc];
                v += __shfl_xor_sync(0xffffffffu, v, 1);
                v += __shfl_xor_sync(0xffffffffu, v, 2);
                pdl[mt][h][cc] = v;
            }
    if ((l & 3) == 0) {
        int q = l >> 2;
#pragma unroll
        for (int mt = 0; mt < 4; mt++)
#pragma unroll
            for (int h = 0; h < 2; h++) {
                int row = mt*16 + q + 8*h;
#pragma unroll
                for (int cc = 0; cc < 3; cc++)
                    pd_sh[(w*64 + row)*3 + cc] = pdl[mt][h][cc];
            }
    }
    __syncthreads();
    if (tid < 192) {
        int row = tid / 3, cc = tid - row*3;
        float s = 0.f;
#pragma unroll
        for (int ww = 0; ww < 8; ww++) s += pd_sh[(ww*64 + row)*3 + cc];
        g_Pd[(size_t)(base + row)*3 + cc] = 0.25f*s + __ldg(pb2 + cc);
    }
}

// ---------------------------------------------------------------------------
__global__ void __launch_bounds__(512) final_kernel(
    const float* __restrict__ own,
    const float* __restrict__ fc1_w, const float* __restrict__ fc1_b,
    const float* __restrict__ merger_w,
    const float* __restrict__ hstate,
    const float* __restrict__ wih, const float* __restrict__ whh,
    const float* __restrict__ bih, const float* __restrict__ bhh,
    const float* __restrict__ fc2_w1, const float* __restrict__ fc2_b1,
    const float* __restrict__ fc2_w2, const float* __restrict__ fc2_b2,
    float* __restrict__ out_q, float* __restrict__ out_h) {
    __shared__ float own_sh[8][32], x_sh[8][64], h_sh[8][64], hh_sh[8][64], t_sh[8][64];
    const int tid = threadIdx.x;
    const int a = tid >> 6, j = tid & 63;
    const int r = blockIdx.x * 8 + a;

    if (j < 30) own_sh[a][j] = own[r*30 + j];
    h_sh[a][j] = hstate[r*64 + j];
    __syncthreads();

    float eo = fc1_b[j];
#pragma unroll
    for (int i = 0; i < 30; i += 2) {
        eo = fmaf(own_sh[a][i], __ldg(fc1_w + i*64 + j), eo);
        eo = fmaf(own_sh[a][i+1], __ldg(fc1_w + (i+1)*64 + j), eo);
    }
    float w0 = merger_w[j], w1v = merger_w[64+j], w2v = merger_w[128+j], w3v = merger_w[192+j];
    float mx = fmaxf(fmaxf(w0, w1v), fmaxf(w2v, w3v));
    float e0 = expf(w0-mx), e1 = expf(w1v-mx), e2 = expf(w2v-mx), e3 = expf(w3v-mx);
    float inv = 1.f / (e0+e1+e2+e3);
    const float* en = g_EmbEn + r*OD;
    const float* al = g_EmbAlSum + r*OD;
    float m = e0*inv*(en[j] + al[j]) + e1*inv*(en[64+j] + al[64+j])
            + e2*inv*(en[128+j] + al[128+j]) + e3*inv*(en[192+j] + al[192+j]);
    x_sh[a][j] = fmaxf(eo + m, 0.f);
    __syncthreads();

    float gi[3], gh[3];
#pragma unroll
    for (int t = 0; t < 3; t++) {
        int g = t*64 + j;
        float si0 = bih[g], si1 = 0.f, sh0 = bhh[g], sh1 = 0.f;
        const float4* wi4 = (const float4*)(wih + g*64);
        const float4* wh4 = (const float4*)(whh + g*64);
#pragma unroll
        for (int k4 = 0; k4 < 16; k4 += 2) {
            float4 a0 = __ldg(wi4 + k4), a1 = __ldg(wi4 + k4 + 1);
            float4 b0 = __ldg(wh4 + k4), b1 = __ldg(wh4 + k4 + 1);
            int kb = 4*k4;
            si0 = fmaf(x_sh[a][kb+0], a0.x, si0); si1 = fmaf(x_sh[a][kb+4], a1.x, si1);
            si0 = fmaf(x_sh[a][kb+1], a0.y, si0); si1 = fmaf(x_sh[a][kb+5], a1.y, si1);
            si0 = fmaf(x_sh[a][kb+2], a0.z, si0); si1 = fmaf(x_sh[a][kb+6], a1.z, si1);
            si0 = fmaf(x_sh[a][kb+3], a0.w, si0); si1 = fmaf(x_sh[a][kb+7], a1.w, si1);
            sh0 = fmaf(h_sh[a][kb+0], b0.x, sh0); sh1 = fmaf(h_sh[a][kb+4], b1.x, sh1);
            sh0 = fmaf(h_sh[a][kb+1], b0.y, sh0); sh1 = fmaf(h_sh[a][kb+5], b1.y, sh1);
            sh0 = fmaf(h_sh[a][kb+2], b0.z, sh0); sh1 = fmaf(h_sh[a][kb+6], b1.z, sh1);
            sh0 = fmaf(h_sh[a][kb+3], b0.w, sh0); sh1 = fmaf(h_sh[a][kb+7], b1.w, sh1);
        }
        gi[t] = si0 + si1; gh[t] = sh0 + sh1;
    }
    float rg = 1.f/(1.f + expf(-(gi[0]+gh[0])));
    float zg = 1.f/(1.f + expf(-(gi[1]+gh[1])));
    float ng = tanhf(gi[2] + rg*gh[2]);
    float hh = (1.f - zg)*ng + zg*h_sh[a][j];
    hh_sh[a][j] = hh;
    out_h[r*64 + j] = hh;
    __syncthreads();

    float tt0 = fc2_b1[j], tt1 = 0.f;
#pragma unroll
    for (int k = 0; k < 64; k += 2) {
        tt0 = fmaf(hh_sh[a][k],   __ldg(fc2_w1 + k*64 + j),     tt0);
        tt1 = fmaf(hh_sh[a][k+1], __ldg(fc2_w1 + (k+1)*64 + j), tt1);
    }
    t_sh[a][j] = fmaxf(tt0 + tt1, 0.f);
    __syncthreads();

    if (j < 19) {
        float q0 = fc2_b2[j], q1 = 0.f;
#pragma unroll
        for (int mm = 0; mm < 64; mm += 2) {
            q0 = fmaf(t_sh[a][mm],   __ldg(fc2_w2 + mm*19 + j),     q0);
            q1 = fmaf(t_sh[a][mm+1], __ldg(fc2_w2 + (mm+1)*19 + j), q1);
        }
        int col = (j < 9) ? j : j + 3;
        out_q[r*22 + col] = q0 + q1;
    }
    if (j < 3) {
        float mxp = -INFINITY;
        for (int q = 0; q < NALLY; q++)
            mxp = fmaxf(mxp, g_Pd[(size_t)(r*NALLY + q)*3 + j]);
        out_q[r*22 + 9 + j] = mxp;
    }
}

extern "C" void kernel_launch(void* const* d_in, const int* in_sizes, int n_in,
                              void* d_out, int out_size) {
    const float* own    = (const float*)d_in[1];
    const float* ally   = (const float*)d_in[2];
    const float* enemy  = (const float*)d_in[3];
    const float* hstate = (const float*)d_in[4];
    const float* fc1_w  = (const float*)d_in[5];
    const float* fc1_b  = (const float*)d_in[6];
    const float* he_w1  = (const float*)d_in[7];
    const float* he_b1  = (const float*)d_in[8];
    const float* he_w2  = (const float*)d_in[9];
    const float* he_b2  = (const float*)d_in[10];
    const float* ha_w1  = (const float*)d_in[11];
    const float* ha_b1  = (const float*)d_in[12];
    const float* ha_w2  = (const float*)d_in[13];
    const float* ha_b2  = (const float*)d_in[14];
    const float* merger = (const float*)d_in[15];
    const float* wih    = (const float*)d_in[16];
    const float* whh    = (const float*)d_in[17];
    const float* bih    = (const float*)d_in[18];
    const float* bhh    = (const float*)d_in[19];
    const float* fc2_w1 = (const float*)d_in[20];
    const float* fc2_b1 = (const float*)d_in[21];
    const float* fc2_w2 = (const float*)d_in[22];
    const float* fc2_b2 = (const float*)d_in[23];
    const float* pw1    = (const float*)d_in[24];
    const float* pb1    = (const float*)d_in[25];
    const float* pw2    = (const float*)d_in[26];
    const float* pb2    = (const float*)d_in[27];

    float* out   = (float*)d_out;
    float* out_q = out;              // [2048, 22]
    float* out_h = out + RR*22;      // [2048, 64]

    wgen_kernel<<<3*KPAD, 256>>>(he_w2, he_b2, ha_w2, ha_b2, pw1);
    repack_kernel<<<1056, 256>>>();
    asum_kernel<<<256, 128>>>(enemy, ally, he_w1, he_b1, ha_w1, ha_b1);
    gemm_sum_kernel<<<64, 256>>>();
    ally_mma_kernel<<<480, 256>>>(ally, ha_w1, ha_b1, pb1, pw2, pb2);
    final_kernel<<<RR/8, 512>>>(own, fc1_w, fc1_b, merger, hstate,
                                wih, whh, bih, bhh,
                                fc2_w1, fc2_b1, fc2_w2, fc2_b2,
                                out_q, out_h);
}

// round 13
// speedup vs baseline: 1.0656x; 1.0656x over previous
#include <cuda_runtime.h>
#include <cuda_bf16.h>
#include <math.h>

#define RR 2048
#define NALLY 15
#define OD 256
#define FD 10
#define KK 650
#define KPAD 704
#define NCHUNK 11
#define ASTR 144

typedef unsigned int u32;
typedef __nv_bfloat16 bf16;

__device__ float g_EmbEn[RR*OD];
__device__ float g_EmbAlSum[RR*OD];
__device__ float g_Pd[RR*NALLY*3];
__device__ u32  g_Bfhi[3*90112], g_Bflo[3*90112];   // mma B fragments (layout verified in R12)

__device__ __forceinline__ u32 smem_u32(const void* p) {
    u32 a; asm("{ .reg .u64 t; cvta.to.shared.u64 t, %1; cvt.u32.u64 %0, t; }" : "=r"(a) : "l"(p)); return a;
}
__device__ __forceinline__ void ldmA(u32* r, u32 addr) {
    asm volatile("ldmatrix.sync.aligned.m8n8.x4.shared.b16 {%0,%1,%2,%3}, [%4];"
        : "=r"(r[0]), "=r"(r[1]), "=r"(r[2]), "=r"(r[3]) : "r"(addr));
}
__device__ __forceinline__ void mma16816(float* d, const u32* a, const u32* b) {
    asm volatile("mma.sync.aligned.m16n8k16.row.col.f32.bf16.bf16.f32 "
        "{%0,%1,%2,%3},{%4,%5,%6,%7},{%8,%9},{%0,%1,%2,%3};"
        : "+f"(d[0]), "+f"(d[1]), "+f"(d[2]), "+f"(d[3])
        : "r"(a[0]), "r"(a[1]), "r"(a[2]), "r"(a[3]), "r"(b[0]), "r"(b[1]));
}
__device__ __forceinline__ void split_bf16(float x, unsigned short& h, unsigned short& l) {
    bf16 hb = __float2bfloat16(x);
    bf16 lb = __float2bfloat16(x - __bfloat162float(hb));
    h = __bfloat16_as_ushort(hb); l = __bfloat16_as_ushort(lb);
}

// ---------------------------------------------------------------------------
// Weight fragments directly: block = (mat, ks). mat0=W2p(folded), 1=enemy, 2=ally.
__global__ void __launch_bounds__(256) wfrag_kernel(
    const float* __restrict__ he_w2, const float* __restrict__ he_b2,
    const float* __restrict__ ha_w2, const float* __restrict__ ha_b2,
    const float* __restrict__ pw1) {
    __shared__ float raw[16][256];
    __shared__ unsigned short whi[16][256], wlo[16][256];
    const int mat = blockIdx.x / 44, ks = blockIdx.x % 44;
    const int tid = threadIdx.x;

    // stage 16 raw rows (fold source for mat0 is ally weights)
#pragma unroll 4
    for (int r = 0; r < 16; r++) {
        int kk = ks*16 + r;
        float v = 0.f;
        if (kk < KK) {
            if (mat == 1) v = (kk < 640) ? he_w2[(size_t)(kk/10)*2820 + (kk%10)*256 + tid]
                                         : he_b2[(size_t)(kk-640)*256 + tid];
            else          v = (kk < 640) ? ha_w2[(size_t)(kk/10)*2560 + (kk%10)*256 + tid]
                                         : ha_b2[(size_t)(kk-640)*256 + tid];
        }
        raw[r][tid] = v;
    }
    __syncthreads();

    if (mat == 0) {
        const int hd = tid >> 6, j = tid & 63;
#pragma unroll 2
        for (int r = 0; r < 16; r++) {
            float s = 0.f;
#pragma unroll
            for (int h = 0; h < 64; h++) s = fmaf(raw[r][hd*64 + h], __ldg(pw1 + h*64 + j), s);
            split_bf16(s, whi[r][tid], wlo[r][tid]);
        }
    } else {
#pragma unroll 4
        for (int r = 0; r < 16; r++) split_bf16(raw[r][tid], whi[r][tid], wlo[r][tid]);
    }
    __syncthreads();

    // emit fragments (same layout as R12-verified repack)
    const size_t obase = (size_t)mat*90112 + (size_t)ks*2048;
#pragma unroll
    for (int u = 0; u < 8; u++) {
        int f = u*256 + tid;
        int nt = f >> 6, l = (f >> 1) & 31, wd = f & 1;
        int kl = (l & 3)*2 + wd*8;
        int n  = nt*8 + (l >> 2);
        g_Bfhi[obase + f] = ((u32)whi[kl+1][n] << 16) | whi[kl][n];
        g_Bflo[obase + f] = ((u32)wlo[kl+1][n] << 16) | wlo[kl][n];
    }
}

// ---------------------------------------------------------------------------
// Summed GEMM with fused A build: 128 blocks (64 enemy + 64 ally), 32 agents each.
__global__ void __launch_bounds__(256) gemm_sum_kernel(
    const float* __restrict__ enemy, const float* __restrict__ ally,
    const float* __restrict__ eW1, const float* __restrict__ eB1,
    const float* __restrict__ aW1, const float* __restrict__ aB1) {
    __shared__ float e_sh[32*161];            // 20.6KB
    __shared__ __align__(16) char smA[9216];  // hi 4608 + lo 4608
    __shared__ float w1s[640], b1s[64];
    const int tid = threadIdx.x, w = tid >> 5, l = tid & 31;
    const bool EN = blockIdx.x < 64;
    const int rowbase = (EN ? blockIdx.x : blockIdx.x - 64) * 32;
    const float* feats = EN ? enemy : ally;
    const float* W1 = EN ? eW1 : aW1;
    const float* B1 = EN ? eB1 : aB1;
    const int per = EN ? 160 : 150;
    const u32 sb = smem_u32(smA);
    const int mat = EN ? 1 : 2;
    const uint2* bfh = (const uint2*)g_Bfhi + (size_t)mat*45056;
    const uint2* bfl = (const uint2*)g_Bflo + (size_t)mat*45056;

    for (int idx = tid; idx < 32*160; idx += 256) {
        int a = idx / 160, rem = idx - a*160;
        e_sh[a*161 + rem] = (rem < per) ? feats[(size_t)(rowbase + a)*per + rem] : 0.f;
    }
    for (int idx = tid; idx < 640; idx += 256) w1s[idx] = __ldg(W1 + idx);
    if (tid < 64) b1s[tid] = B1[tid];
    __syncthreads();

    const int a32 = tid & 31, part = tid >> 5;   // 8 parts x 8 klanes
    const float* ea = e_sh + a32*161;

    float d[2][4][4];
#pragma unroll
    for (int a = 0; a < 2; a++)
#pragma unroll
        for (int b = 0; b < 4; b++)
#pragma unroll
            for (int q = 0; q < 4; q++) d[a][b][q] = 0.f;

    for (int c = 0; c < NCHUNK; c++) {
        __syncthreads();
        // build 8 klanes for agent a32 (row-summed A, split bf16)
        unsigned short hi8[8], lo8[8];
        int kcur = -1;
        float h[16];
#pragma unroll
        for (int u = 0; u < 8; u++) {
            int kk = c*64 + part*8 + u;
            float x;
            if (kk < 640) {
                int k = (kk*6554) >> 16, i = kk - k*10;
                if (k != kcur) {
                    kcur = k;
#pragma unroll
                    for (int rr = 0; rr < 16; rr++) {
                        float s = b1s[k];
#pragma unroll
                        for (int ii = 0; ii < FD; ii++) s = fmaf(ea[rr*FD + ii], w1s[ii*64 + k], s);
                        h[rr] = fmaxf(s, 0.f);
                    }
                }
                float s = 0.f;
#pragma unroll
                for (int rr = 0; rr < 16; rr++) s = fmaf(h[rr], ea[rr*FD + i], s);
                x = s;
            } else if (kk < KK) {
                float s = 0.f;
#pragma unroll
                for (int rr = 0; rr < 16; rr++) s += ea[rr*FD + (kk - 640)];
                x = s;
            } else x = 0.f;
            split_bf16(x, hi8[u], lo8[u]);
        }
        {
            int off = a32*ASTR + part*16;
            *(uint4*)(smA + off) = make_uint4(
                ((u32)hi8[1]<<16)|hi8[0], ((u32)hi8[3]<<16)|hi8[2],
                ((u32)hi8[5]<<16)|hi8[4], ((u32)hi8[7]<<16)|hi8[6]);
            *(uint4*)(smA + 4608 + off) = make_uint4(
                ((u32)lo8[1]<<16)|lo8[0], ((u32)lo8[3]<<16)|lo8[2],
                ((u32)lo8[5]<<16)|lo8[4], ((u32)lo8[7]<<16)|lo8[6]);
        }
        __syncthreads();

        const u32 aRow = (u32)((l & 15)*ASTR + (l >> 4)*16);
#pragma unroll
        for (int kt = 0; kt < 4; kt++) {
            u32 ah[2][4], al_[2][4];
#pragma unroll
            for (int mt = 0; mt < 2; mt++) {
                u32 ab = (u32)(mt*16*ASTR + kt*32) + aRow;
                ldmA(ah[mt],  sb + ab);
                ldmA(al_[mt], sb + 4608 + ab);
            }
            const size_t fb = ((size_t)(c*4 + kt)*32 + w*4)*32 + l;
#pragma unroll
            for (int nt = 0; nt < 4; nt++) {
                uint2 bhv = __ldg(bfh + fb + nt*32);
                uint2 blv = __ldg(bfl + fb + nt*32);
                u32 bh[2] = {bhv.x, bhv.y}, bl[2] = {blv.x, blv.y};
#pragma unroll
                for (int mt = 0; mt < 2; mt++) mma16816(d[mt][nt], ah[mt],  bh);
#pragma unroll
                for (int mt = 0; mt < 2; mt++) mma16816(d[mt][nt], ah[mt],  bl);
#pragma unroll
                for (int mt = 0; mt < 2; mt++) mma16816(d[mt][nt], al_[mt], bh);
            }
        }
    }
    float* outp = EN ? g_EmbEn : g_EmbAlSum;
#pragma unroll
    for (int mt = 0; mt < 2; mt++)
#pragma unroll
        for (int nt = 0; nt < 4; nt++)
#pragma unroll
            for (int q = 0; q < 4; q++) {
                int row = rowbase + mt*16 + (l >> 2) + (q >> 1)*8;
                int col = (w*4 + nt)*8 + (l & 3)*2 + (q & 1);
                outp[(size_t)row*OD + col] = d[mt][nt][q];
            }
}

// ---------------------------------------------------------------------------
// Ally layer-1 GEMM (A built in-kernel) + fused relu/pw2/head-mean (R12, passing).
#define SA_HI 0
#define SA_LO 9216
#define SE    18432
#define SH    20992
#define SW1   23040
#define SB1   25600
#define SPWE  25856
#define SPD   26880
__global__ void __launch_bounds__(256) ally_mma_kernel(
    const float* __restrict__ feats, const float* __restrict__ W1, const float* __restrict__ B1,
    const float* __restrict__ pb1, const float* __restrict__ pw2, const float* __restrict__ pb2)
{
    __shared__ __align__(16) char smem[33024];
    const int tid = threadIdx.x, w = tid >> 5, l = tid & 31;
    const u32 sb = smem_u32(smem);
    const int base = blockIdx.x * 64;

    float* e_sh  = (float*)(smem + SE);
    float* h_sh  = (float*)(smem + SH);
    float* w1_sh = (float*)(smem + SW1);
    float* b1_sh = (float*)(smem + SB1);
    float* pwe   = (float*)(smem + SPWE);
    float* pd_sh = (float*)(smem + SPD);

    for (int idx = tid; idx < 640; idx += 256) {
        int m = idx / 10, i = idx - m*10;
        e_sh[i*64 + m] = __ldg(feats + (size_t)base*FD + idx);
        w1_sh[idx] = __ldg(W1 + idx);
    }
    if (tid < 64) b1_sh[tid] = B1[tid];
    pwe[tid] = (tid < 64) ? __ldg(pb1 + tid) : __ldg(pw2 + tid - 64);
    __syncthreads();

    const uint2* bfh = (const uint2*)g_Bfhi;   // mat 0 = W2p
    const uint2* bfl = (const uint2*)g_Bflo;

    float d[4][4][4];
#pragma unroll
    for (int a = 0; a < 4; a++)
#pragma unroll
        for (int b = 0; b < 4; b++)
#pragma unroll
            for (int q = 0; q < 4; q++) d[a][b][q] = 0.f;

    const int m64 = tid & 63, part = tid >> 6;

    for (int c = 0; c < NCHUNK; c++) {
        __syncthreads();
        const int k0 = (c*64) / 10;
        const int kcnt = (c < 10) ? ((c*64 + 63)/10 - k0 + 1) : 0;
        for (int idx = tid; idx < kcnt*64; idx += 256) {
            int kr = idx >> 6, mm = idx & 63;
            float s = b1_sh[k0 + kr];
#pragma unroll
            for (int i = 0; i < FD; i++) s = fmaf(e_sh[i*64 + mm], w1_sh[i*64 + k0 + kr], s);
            h_sh[kr*64 + mm] = fmaxf(s, 0.f);
        }
        if (kcnt) __syncthreads();

        {
            u32 hi[8], lo[8];
#pragma unroll
            for (int u = 0; u < 8; u++) {
                unsigned short hs[2], ls[2];
#pragma unroll
                for (int v2 = 0; v2 < 2; v2++) {
                    int kk = c*64 + part*16 + 2*u + v2;
                    float xv;
                    if (kk < 640) {
                        int k = (kk*6554) >> 16, i = kk - k*10;
                        xv = h_sh[(k - k0)*64 + m64] * e_sh[i*64 + m64];
                    } else if (kk < KK) xv = e_sh[(kk - 640)*64 + m64];
                    else xv = 0.f;
                    split_bf16(xv, hs[v2], ls[v2]);
                }
                hi[u] = ((u32)hs[1] << 16) | hs[0];
                lo[u] = ((u32)ls[1] << 16) | ls[0];
            }
            int off = m64*ASTR + part*32;
            *(uint4*)(smem + SA_HI + off)      = make_uint4(hi[0], hi[1], hi[2], hi[3]);
            *(uint4*)(smem + SA_HI + off + 16) = make_uint4(hi[4], hi[5], hi[6], hi[7]);
            *(uint4*)(smem + SA_LO + off)      = make_uint4(lo[0], lo[1], lo[2], lo[3]);
            *(uint4*)(smem + SA_LO + off + 16) = make_uint4(lo[4], lo[5], lo[6], lo[7]);
        }
        __syncthreads();

        const u32 aRow = (u32)((l & 15)*ASTR + (l >> 4)*16);
#pragma unroll
        for (int kt = 0; kt < 4; kt++) {
            u32 ah[4][4], al_[4][4];
#pragma unroll
            for (int mt = 0; mt < 4; mt++) {
                u32 ab = (u32)(mt*16*ASTR + kt*32) + aRow;
                ldmA(ah[mt],  sb + SA_HI + ab);
                ldmA(al_[mt], sb + SA_LO + ab);
            }
            const size_t fb = ((size_t)(c*4 + kt)*32 + w*4)*32 + l;
#pragma unroll
            for (int nt = 0; nt < 4; nt++) {
                uint2 bhv = __ldg(bfh + fb + nt*32);
                uint2 blv = __ldg(bfl + fb + nt*32);
                u32 bh[2] = {bhv.x, bhv.y}, bl[2] = {blv.x, blv.y};
#pragma unroll
                for (int mt = 0; mt < 4; mt++) mma16816(d[mt][nt], ah[mt],  bh);
#pragma unroll
                for (int mt = 0; mt < 4; mt++) mma16816(d[mt][nt], ah[mt],  bl);
#pragma unroll
                for (int mt = 0; mt < 4; mt++) mma16816(d[mt][nt], al_[mt], bh);
            }
        }
    }

    float pdl[4][2][3];
#pragma unroll
    for (int mt = 0; mt < 4; mt++)
#pragma unroll
        for (int h = 0; h < 2; h++)
#pragma unroll
            for (int cc = 0; cc < 3; cc++) pdl[mt][h][cc] = 0.f;
#pragma unroll
    for (int mt = 0; mt < 4; mt++)
#pragma unroll
        for (int nt = 0; nt < 4; nt++) {
            int colA = (w*4 + nt)*8 + (l & 3)*2;
            int jA = colA & 63, jB = (colA + 1) & 63;
#pragma unroll
            for (int h = 0; h < 2; h++) {
                float t0 = fmaxf(d[mt][nt][2*h    ] + pwe[jA], 0.f);
                float t1 = fmaxf(d[mt][nt][2*h + 1] + pwe[jB], 0.f);
#pragma unroll
                for (int cc = 0; cc < 3; cc++) {
                    pdl[mt][h][cc] = fmaf(t0, pwe[64 + jA*3 + cc], pdl[mt][h][cc]);
                    pdl[mt][h][cc] = fmaf(t1, pwe[64 + jB*3 + cc], pdl[mt][h][cc]);
                }
            }
        }
#pragma unroll
    for (int mt = 0; mt < 4; mt++)
#pragma unroll
        for (int h = 0; h < 2; h++)
#pragma unroll
            for (int cc = 0; cc < 3; cc++) {
                float v = pdl[mt][h][cc];
                v += __shfl_xor_sync(0xffffffffu, v, 1);
                v += __shfl_xor_sync(0xffffffffu, v, 2);
                pdl[mt][h][cc] = v;
            }
    if ((l & 3) == 0) {
        int q = l >> 2;
#pragma unroll
        for (int mt = 0; mt < 4; mt++)
#pragma unroll
            for (int h = 0; h < 2; h++) {
                int row = mt*16 + q + 8*h;
#pragma unroll
                for (int cc = 0; cc < 3; cc++)
                    pd_sh[(w*64 + row)*3 + cc] = pdl[mt][h][cc];
            }
    }
    __syncthreads();
    if (tid < 192) {
        int row = tid / 3, cc = tid - row*3;
        float s = 0.f;
#pragma unroll
        for (int ww = 0; ww < 8; ww++) s += pd_sh[(ww*64 + row)*3 + cc];
        g_Pd[(size_t)(base + row)*3 + cc] = 0.25f*s + __ldg(pb2 + cc);
    }
}

// ---------------------------------------------------------------------------
__global__ void __launch_bounds__(512) final_kernel(
    const float* __restrict__ own,
    const float* __restrict__ fc1_w, const float* __restrict__ fc1_b,
    const float* __restrict__ merger_w,
    const float* __restrict__ hstate,
    const float* __restrict__ wih, const float* __restrict__ whh,
    const float* __restrict__ bih, const float* __restrict__ bhh,
    const float* __restrict__ fc2_w1, const float* __restrict__ fc2_b1,
    const float* __restrict__ fc2_w2, const float* __restrict__ fc2_b2,
    float* __restrict__ out_q, float* __restrict__ out_h) {
    __shared__ float own_sh[8][32], x_sh[8][64], h_sh[8][64], hh_sh[8][64], t_sh[8][64];
    const int tid = threadIdx.x;
    const int a = tid >> 6, j = tid & 63;
    const int r = blockIdx.x * 8 + a;

    if (j < 30) own_sh[a][j] = own[r*30 + j];
    h_sh[a][j] = hstate[r*64 + j];
    __syncthreads();

    float eo = fc1_b[j];
#pragma unroll
    for (int i = 0; i < 30; i += 2) {
        eo = fmaf(own_sh[a][i], __ldg(fc1_w + i*64 + j), eo);
        eo = fmaf(own_sh[a][i+1], __ldg(fc1_w + (i+1)*64 + j), eo);
    }
    float w0 = merger_w[j], w1v = merger_w[64+j], w2v = merger_w[128+j], w3v = merger_w[192+j];
    float mx = fmaxf(fmaxf(w0, w1v), fmaxf(w2v, w3v));
    float e0 = expf(w0-mx), e1 = expf(w1v-mx), e2 = expf(w2v-mx), e3 = expf(w3v-mx);
    float inv = 1.f / (e0+e1+e2+e3);
    const float* en = g_EmbEn + r*OD;
    const float* al = g_EmbAlSum + r*OD;
    float m = e0*inv*(en[j] + al[j]) + e1*inv*(en[64+j] + al[64+j])
            + e2*inv*(en[128+j] + al[128+j]) + e3*inv*(en[192+j] + al[192+j]);
    x_sh[a][j] = fmaxf(eo + m, 0.f);
    __syncthreads();

    float gi[3], gh[3];
#pragma unroll
    for (int t = 0; t < 3; t++) {
        int g = t*64 + j;
        float si0 = bih[g], si1 = 0.f, sh0 = bhh[g], sh1 = 0.f;
        const float4* wi4 = (const float4*)(wih + g*64);
        const float4* wh4 = (const float4*)(whh + g*64);
#pragma unroll
        for (int k4 = 0; k4 < 16; k4 += 2) {
            float4 a0 = __ldg(wi4 + k4), a1 = __ldg(wi4 + k4 + 1);
            float4 b0 = __ldg(wh4 + k4), b1 = __ldg(wh4 + k4 + 1);
            int kb = 4*k4;
            si0 = fmaf(x_sh[a][kb+0], a0.x, si0); si1 = fmaf(x_sh[a][kb+4], a1.x, si1);
            si0 = fmaf(x_sh[a][kb+1], a0.y, si0); si1 = fmaf(x_sh[a][kb+5], a1.y, si1);
            si0 = fmaf(x_sh[a][kb+2], a0.z, si0); si1 = fmaf(x_sh[a][kb+6], a1.z, si1);
            si0 = fmaf(x_sh[a][kb+3], a0.w, si0); si1 = fmaf(x_sh[a][kb+7], a1.w, si1);
            sh0 = fmaf(h_sh[a][kb+0], b0.x, sh0); sh1 = fmaf(h_sh[a][kb+4], b1.x, sh1);
            sh0 = fmaf(h_sh[a][kb+1], b0.y, sh0); sh1 = fmaf(h_sh[a][kb+5], b1.y, sh1);
            sh0 = fmaf(h_sh[a][kb+2], b0.z, sh0); sh1 = fmaf(h_sh[a][kb+6], b1.z, sh1);
            sh0 = fmaf(h_sh[a][kb+3], b0.w, sh0); sh1 = fmaf(h_sh[a][kb+7], b1.w, sh1);
        }
        gi[t] = si0 + si1; gh[t] = sh0 + sh1;
    }
    float rg = 1.f/(1.f + expf(-(gi[0]+gh[0])));
    float zg = 1.f/(1.f + expf(-(gi[1]+gh[1])));
    float ng = tanhf(gi[2] + rg*gh[2]);
    float hh = (1.f - zg)*ng + zg*h_sh[a][j];
    hh_sh[a][j] = hh;
    out_h[r*64 + j] = hh;
    __syncthreads();

    float tt0 = fc2_b1[j], tt1 = 0.f;
#pragma unroll
    for (int k = 0; k < 64; k += 2) {
        tt0 = fmaf(hh_sh[a][k],   __ldg(fc2_w1 + k*64 + j),     tt0);
        tt1 = fmaf(hh_sh[a][k+1], __ldg(fc2_w1 + (k+1)*64 + j), tt1);
    }
    t_sh[a][j] = fmaxf(tt0 + tt1, 0.f);
    __syncthreads();

    if (j < 19) {
        float q0 = fc2_b2[j], q1 = 0.f;
#pragma unroll
        for (int mm = 0; mm < 64; mm += 2) {
            q0 = fmaf(t_sh[a][mm],   __ldg(fc2_w2 + mm*19 + j),     q0);
            q1 = fmaf(t_sh[a][mm+1], __ldg(fc2_w2 + (mm+1)*19 + j), q1);
        }
        int col = (j < 9) ? j : j + 3;
        out_q[r*22 + col] = q0 + q1;
    }
    if (j < 3) {
        float mxp = -INFINITY;
        for (int q = 0; q < NALLY; q++)
            mxp = fmaxf(mxp, g_Pd[(size_t)(r*NALLY + q)*3 + j]);
        out_q[r*22 + 9 + j] = mxp;
    }
}

extern "C" void kernel_launch(void* const* d_in, const int* in_sizes, int n_in,
                              void* d_out, int out_size) {
    const float* own    = (const float*)d_in[1];
    const float* ally   = (const float*)d_in[2];
    const float* enemy  = (const float*)d_in[3];
    const float* hstate = (const float*)d_in[4];
    const float* fc1_w  = (const float*)d_in[5];
    const float* fc1_b  = (const float*)d_in[6];
    const float* he_w1  = (const float*)d_in[7];
    const float* he_b1  = (const float*)d_in[8];
    const float* he_w2  = (const float*)d_in[9];
    const float* he_b2  = (const float*)d_in[10];
    const float* ha_w1  = (const float*)d_in[11];
    const float* ha_b1  = (const float*)d_in[12];
    const float* ha_w2  = (const float*)d_in[13];
    const float* ha_b2  = (const float*)d_in[14];
    const float* merger = (const float*)d_in[15];
    const float* wih    = (const float*)d_in[16];
    const float* whh    = (const float*)d_in[17];
    const float* bih    = (const float*)d_in[18];
    const float* bhh    = (const float*)d_in[19];
    const float* fc2_w1 = (const float*)d_in[20];
    const float* fc2_b1 = (const float*)d_in[21];
    const float* fc2_w2 = (const float*)d_in[22];
    const float* fc2_b2 = (const float*)d_in[23];
    const float* pw1    = (const float*)d_in[24];
    const float* pb1    = (const float*)d_in[25];
    const float* pw2    = (const float*)d_in[26];
    const float* pb2    = (const float*)d_in[27];

    float* out   = (float*)d_out;
    float* out_q = out;              // [2048, 22]
    float* out_h = out + RR*22;      // [2048, 64]

    wfrag_kernel<<<3*44, 256>>>(he_w2, he_b2, ha_w2, ha_b2, pw1);
    gemm_sum_kernel<<<128, 256>>>(enemy, ally, he_w1, he_b1, ha_w1, ha_b1);
    ally_mma_kernel<<<480, 256>>>(ally, ha_w1, ha_b1, pb1, pw2, pb2);
    final_kernel<<<RR/8, 512>>>(own, fc1_w, fc1_b, merger, hstate,
                                wih, whh, bih, bhh,
                                fc2_w1, fc2_b1, fc2_w2, fc2_b2,
                                out_q, out_h);
}

// round 17
// speedup vs baseline: 1.2658x; 1.1878x over previous
#include <cuda_runtime.h>
#include <cuda_bf16.h>
#include <math.h>

#define RR 2048
#define NALLY 15
#define OD 256
#define FD 10
#define KK 650
#define KPAD 704
#define NCHUNK 11
#define ASTR 144

typedef unsigned int u32;
typedef __nv_bfloat16 bf16;

__device__ float g_EmbEn[RR*OD];
__device__ float g_EmbAlSum[RR*OD];
__device__ float g_Pd[RR*NALLY*3];
__device__ u32  g_Bfhi[3*90112], g_Bflo[3*90112];   // mma B fragments (layout verified in R12)

__device__ __forceinline__ u32 smem_u32(const void* p) {
    u32 a; asm("{ .reg .u64 t; cvta.to.shared.u64 t, %1; cvt.u32.u64 %0, t; }" : "=r"(a) : "l"(p)); return a;
}
__device__ __forceinline__ void ldmA(u32* r, u32 addr) {
    asm volatile("ldmatrix.sync.aligned.m8n8.x4.shared.b16 {%0,%1,%2,%3}, [%4];"
        : "=r"(r[0]), "=r"(r[1]), "=r"(r[2]), "=r"(r[3]) : "r"(addr));
}
__device__ __forceinline__ void mma16816(float* d, const u32* a, const u32* b) {
    asm volatile("mma.sync.aligned.m16n8k16.row.col.f32.bf16.bf16.f32 "
        "{%0,%1,%2,%3},{%4,%5,%6,%7},{%8,%9},{%0,%1,%2,%3};"
        : "+f"(d[0]), "+f"(d[1]), "+f"(d[2]), "+f"(d[3])
        : "r"(a[0]), "r"(a[1]), "r"(a[2]), "r"(a[3]), "r"(b[0]), "r"(b[1]));
}
__device__ __forceinline__ void split_bf16(float x, unsigned short& h, unsigned short& l) {
    bf16 hb = __float2bfloat16(x);
    bf16 lb = __float2bfloat16(x - __bfloat162float(hb));
    h = __bfloat16_as_ushort(hb); l = __bfloat16_as_ushort(lb);
}

// ---------------------------------------------------------------------------
// Weight fragments: block = (mat, ks). mat0=W2p(folded), 1=enemy, 2=ally.
__global__ void __launch_bounds__(256) wfrag_kernel(
    const float* __restrict__ he_w2, const float* __restrict__ he_b2,
    const float* __restrict__ ha_w2, const float* __restrict__ ha_b2,
    const float* __restrict__ pw1) {
    __shared__ float raw[16][256];
    __shared__ unsigned short whi[16][256], wlo[16][256];
    const int mat = blockIdx.x / 44, ks = blockIdx.x % 44;
    const int tid = threadIdx.x;

#pragma unroll 4
    for (int r = 0; r < 16; r++) {
        int kk = ks*16 + r;
        float v = 0.f;
        if (kk < KK) {
            if (mat == 1) v = (kk < 640) ? he_w2[(size_t)(kk/10)*2820 + (kk%10)*256 + tid]
                                         : he_b2[(size_t)(kk-640)*256 + tid];
            else          v = (kk < 640) ? ha_w2[(size_t)(kk/10)*2560 + (kk%10)*256 + tid]
                                         : ha_b2[(size_t)(kk-640)*256 + tid];
        }
        raw[r][tid] = v;
    }
    __syncthreads();

    if (mat == 0) {
        const int hd = tid >> 6, j = tid & 63;
#pragma unroll 2
        for (int r = 0; r < 16; r++) {
            float s = 0.f;
#pragma unroll
            for (int h = 0; h < 64; h++) s = fmaf(raw[r][hd*64 + h], __ldg(pw1 + h*64 + j), s);
            split_bf16(s, whi[r][tid], wlo[r][tid]);
        }
    } else {
#pragma unroll 4
        for (int r = 0; r < 16; r++) split_bf16(raw[r][tid], whi[r][tid], wlo[r][tid]);
    }
    __syncthreads();

    const size_t obase = (size_t)mat*90112 + (size_t)ks*2048;
#pragma unroll
    for (int u = 0; u < 8; u++) {
        int f = u*256 + tid;
        int nt = f >> 6, l = (f >> 1) & 31, wd = f & 1;
        int kl = (l & 3)*2 + wd*8;
        int n  = nt*8 + (l >> 2);
        g_Bfhi[obase + f] = ((u32)whi[kl+1][n] << 16) | whi[kl][n];
        g_Bflo[obase + f] = ((u32)wlo[kl+1][n] << 16) | wlo[kl][n];
    }
}

// ---------------------------------------------------------------------------
// Summed GEMM with fused A build (R13, passing)
__global__ void __launch_bounds__(256) gemm_sum_kernel(
    const float* __restrict__ enemy, const float* __restrict__ ally,
    const float* __restrict__ eW1, const float* __restrict__ eB1,
    const float* __restrict__ aW1, const float* __restrict__ aB1) {
    __shared__ float e_sh[32*161];
    __shared__ __align__(16) char smA[9216];
    __shared__ float w1s[640], b1s[64];
    const int tid = threadIdx.x, w = tid >> 5, l = tid & 31;
    const bool EN = blockIdx.x < 64;
    const int rowbase = (EN ? blockIdx.x : blockIdx.x - 64) * 32;
    const float* feats = EN ? enemy : ally;
    const float* W1 = EN ? eW1 : aW1;
    const float* B1 = EN ? eB1 : aB1;
    const int per = EN ? 160 : 150;
    const u32 sb = smem_u32(smA);
    const int mat = EN ? 1 : 2;
    const uint2* bfh = (const uint2*)g_Bfhi + (size_t)mat*45056;
    const uint2* bfl = (const uint2*)g_Bflo + (size_t)mat*45056;

    for (int idx = tid; idx < 32*160; idx += 256) {
        int a = idx / 160, rem = idx - a*160;
        e_sh[a*161 + rem] = (rem < per) ? feats[(size_t)(rowbase + a)*per + rem] : 0.f;
    }
    for (int idx = tid; idx < 640; idx += 256) w1s[idx] = __ldg(W1 + idx);
    if (tid < 64) b1s[tid] = B1[tid];
    __syncthreads();

    const int a32 = tid & 31, part = tid >> 5;
    const float* ea = e_sh + a32*161;

    float d[2][4][4];
#pragma unroll
    for (int a = 0; a < 2; a++)
#pragma unroll
        for (int b = 0; b < 4; b++)
#pragma unroll
            for (int q = 0; q < 4; q++) d[a][b][q] = 0.f;

    for (int c = 0; c < NCHUNK; c++) {
        __syncthreads();
        unsigned short hi8[8], lo8[8];
        int kcur = -1;
        float h[16];
#pragma unroll
        for (int u = 0; u < 8; u++) {
            int kk = c*64 + part*8 + u;
            float x;
            if (kk < 640) {
                int k = (kk*6554) >> 16, i = kk - k*10;
                if (k != kcur) {
                    kcur = k;
#pragma unroll
                    for (int rr = 0; rr < 16; rr++) {
                        float s = b1s[k];
#pragma unroll
                        for (int ii = 0; ii < FD; ii++) s = fmaf(ea[rr*FD + ii], w1s[ii*64 + k], s);
                        h[rr] = fmaxf(s, 0.f);
                    }
                }
                float s = 0.f;
#pragma unroll
                for (int rr = 0; rr < 16; rr++) s = fmaf(h[rr], ea[rr*FD + i], s);
                x = s;
            } else if (kk < KK) {
                float s = 0.f;
#pragma unroll
                for (int rr = 0; rr < 16; rr++) s += ea[rr*FD + (kk - 640)];
                x = s;
            } else x = 0.f;
            split_bf16(x, hi8[u], lo8[u]);
        }
        {
            int off = a32*ASTR + part*16;
            *(uint4*)(smA + off) = make_uint4(
                ((u32)hi8[1]<<16)|hi8[0], ((u32)hi8[3]<<16)|hi8[2],
                ((u32)hi8[5]<<16)|hi8[4], ((u32)hi8[7]<<16)|hi8[6]);
            *(uint4*)(smA + 4608 + off) = make_uint4(
                ((u32)lo8[1]<<16)|lo8[0], ((u32)lo8[3]<<16)|lo8[2],
                ((u32)lo8[5]<<16)|lo8[4], ((u32)lo8[7]<<16)|lo8[6]);
        }
        __syncthreads();

        const u32 aRow = (u32)((l & 15)*ASTR + (l >> 4)*16);
#pragma unroll
        for (int kt = 0; kt < 4; kt++) {
            u32 ah[2][4], al_[2][4];
#pragma unroll
            for (int mt = 0; mt < 2; mt++) {
                u32 ab = (u32)(mt*16*ASTR + kt*32) + aRow;
                ldmA(ah[mt],  sb + ab);
                ldmA(al_[mt], sb + 4608 + ab);
            }
            const size_t fb = ((size_t)(c*4 + kt)*32 + w*4)*32 + l;
#pragma unroll
            for (int nt = 0; nt < 4; nt++) {
                uint2 bhv = __ldg(bfh + fb + nt*32);
                uint2 blv = __ldg(bfl + fb + nt*32);
                u32 bh[2] = {bhv.x, bhv.y}, bl[2] = {blv.x, blv.y};
#pragma unroll
                for (int mt = 0; mt < 2; mt++) mma16816(d[mt][nt], ah[mt],  bh);
#pragma unroll
                for (int mt = 0; mt < 2; mt++) mma16816(d[mt][nt], ah[mt],  bl);
#pragma unroll
                for (int mt = 0; mt < 2; mt++) mma16816(d[mt][nt], al_[mt], bh);
            }
        }
    }
    float* outp = EN ? g_EmbEn : g_EmbAlSum;
#pragma unroll
    for (int mt = 0; mt < 2; mt++)
#pragma unroll
        for (int nt = 0; nt < 4; nt++)
#pragma unroll
            for (int q = 0; q < 4; q++) {
                int row = rowbase + mt*16 + (l >> 2) + (q >> 1)*8;
                int col = (w*4 + nt)*8 + (l & 3)*2 + (q & 1);
                outp[(size_t)row*OD + col] = d[mt][nt][q];
            }
}

// ---------------------------------------------------------------------------
// Ally layer-1 GEMM + fused relu/pw2/head-mean (R13, passing).
#define SA_HI 0
#define SA_LO 9216
#define SE    18432
#define SH    20992
#define SW1   23040
#define SB1   25600
#define SPWE  25856
#define SPD   26880
__global__ void __launch_bounds__(256) ally_mma_kernel(
    const float* __restrict__ feats, const float* __restrict__ W1, const float* __restrict__ B1,
    const float* __restrict__ pb1, const float* __restrict__ pw2, const float* __restrict__ pb2)
{
    __shared__ __align__(16) char smem[33024];
    const int tid = threadIdx.x, w = tid >> 5, l = tid & 31;
    const u32 sb = smem_u32(smem);
    const int base = blockIdx.x * 64;

    float* e_sh  = (float*)(smem + SE);
    float* h_sh  = (float*)(smem + SH);
    float* w1_sh = (float*)(smem + SW1);
    float* b1_sh = (float*)(smem + SB1);
    float* pwe   = (float*)(smem + SPWE);
    float* pd_sh = (float*)(smem + SPD);

    for (int idx = tid; idx < 640; idx += 256) {
        int m = idx / 10, i = idx - m*10;
        e_sh[i*64 + m] = __ldg(feats + (size_t)base*FD + idx);
        w1_sh[idx] = __ldg(W1 + idx);
    }
    if (tid < 64) b1_sh[tid] = B1[tid];
    pwe[tid] = (tid < 64) ? __ldg(pb1 + tid) : __ldg(pw2 + tid - 64);
    __syncthreads();

    const uint2* bfh = (const uint2*)g_Bfhi;
    const uint2* bfl = (const uint2*)g_Bflo;

    float d[4][4][4];
#pragma unroll
    for (int a = 0; a < 4; a++)
#pragma unroll
        for (int b = 0; b < 4; b++)
#pragma unroll
            for (int q = 0; q < 4; q++) d[a][b][q] = 0.f;

    const int m64 = tid & 63, part = tid >> 6;

    for (int c = 0; c < NCHUNK; c++) {
        __syncthreads();
        const int k0 = (c*64) / 10;
        const int kcnt = (c < 10) ? ((c*64 + 63)/10 - k0 + 1) : 0;
        for (int idx = tid; idx < kcnt*64; idx += 256) {
            int kr = idx >> 6, mm = idx & 63;
            float s = b1_sh[k0 + kr];
#pragma unroll
            for (int i = 0; i < FD; i++) s = fmaf(e_sh[i*64 + mm], w1_sh[i*64 + k0 + kr], s);
            h_sh[kr*64 + mm] = fmaxf(s, 0.f);
        }
        if (kcnt) __syncthreads();

        {
            u32 hi[8], lo[8];
#pragma unroll
            for (int u = 0; u < 8; u++) {
                unsigned short hs[2], ls[2];
#pragma unroll
                for (int v2 = 0; v2 < 2; v2++) {
                    int kk = c*64 + part*16 + 2*u + v2;
                    float xv;
                    if (kk < 640) {
                        int k = (kk*6554) >> 16, i = kk - k*10;
                        xv = h_sh[(k - k0)*64 + m64] * e_sh[i*64 + m64];
                    } else if (kk < KK) xv = e_sh[(kk - 640)*64 + m64];
                    else xv = 0.f;
                    split_bf16(xv, hs[v2], ls[v2]);
                }
                hi[u] = ((u32)hs[1] << 16) | hs[0];
                lo[u] = ((u32)ls[1] << 16) | ls[0];
            }
            int off = m64*ASTR + part*32;
            *(uint4*)(smem + SA_HI + off)      = make_uint4(hi[0], hi[1], hi[2], hi[3]);
            *(uint4*)(smem + SA_HI + off + 16) = make_uint4(hi[4], hi[5], hi[6], hi[7]);
            *(uint4*)(smem + SA_LO + off)      = make_uint4(lo[0], lo[1], lo[2], lo[3]);
            *(uint4*)(smem + SA_LO + off + 16) = make_uint4(lo[4], lo[5], lo[6], lo[7]);
        }
        __syncthreads();

        const u32 aRow = (u32)((l & 15)*ASTR + (l >> 4)*16);
#pragma unroll
        for (int kt = 0; kt < 4; kt++) {
            u32 ah[4][4], al_[4][4];
#pragma unroll
            for (int mt = 0; mt < 4; mt++) {
                u32 ab = (u32)(mt*16*ASTR + kt*32) + aRow;
                ldmA(ah[mt],  sb + SA_HI + ab);
                ldmA(al_[mt], sb + SA_LO + ab);
            }
            const size_t fb = ((size_t)(c*4 + kt)*32 + w*4)*32 + l;
#pragma unroll
            for (int nt = 0; nt < 4; nt++) {
                uint2 bhv = __ldg(bfh + fb + nt*32);
                uint2 blv = __ldg(bfl + fb + nt*32);
                u32 bh[2] = {bhv.x, bhv.y}, bl[2] = {blv.x, blv.y};
#pragma unroll
                for (int mt = 0; mt < 4; mt++) mma16816(d[mt][nt], ah[mt],  bh);
#pragma unroll
                for (int mt = 0; mt < 4; mt++) mma16816(d[mt][nt], ah[mt],  bl);
#pragma unroll
                for (int mt = 0; mt < 4; mt++) mma16816(d[mt][nt], al_[mt], bh);
            }
        }
    }

    float pdl[4][2][3];
#pragma unroll
    for (int mt = 0; mt < 4; mt++)
#pragma unroll
        for (int h = 0; h < 2; h++)
#pragma unroll
            for (int cc = 0; cc < 3; cc++) pdl[mt][h][cc] = 0.f;
#pragma unroll
    for (int mt = 0; mt < 4; mt++)
#pragma unroll
        for (int nt = 0; nt < 4; nt++) {
            int colA = (w*4 + nt)*8 + (l & 3)*2;
            int jA = colA & 63, jB = (colA + 1) & 63;
#pragma unroll
            for (int h = 0; h < 2; h++) {
                float t0 = fmaxf(d[mt][nt][2*h    ] + pwe[jA], 0.f);
                float t1 = fmaxf(d[mt][nt][2*h + 1] + pwe[jB], 0.f);
#pragma unroll
                for (int cc = 0; cc < 3; cc++) {
                    pdl[mt][h][cc] = fmaf(t0, pwe[64 + jA*3 + cc], pdl[mt][h][cc]);
                    pdl[mt][h][cc] = fmaf(t1, pwe[64 + jB*3 + cc], pdl[mt][h][cc]);
                }
            }
        }
#pragma unroll
    for (int mt = 0; mt < 4; mt++)
#pragma unroll
        for (int h = 0; h < 2; h++)
#pragma unroll
            for (int cc = 0; cc < 3; cc++) {
                float v = pdl[mt][h][cc];
                v += __shfl_xor_sync(0xffffffffu, v, 1);
                v += __shfl_xor_sync(0xffffffffu, v, 2);
                pdl[mt][h][cc] = v;
            }
    if ((l & 3) == 0) {
        int q = l >> 2;
#pragma unroll
        for (int mt = 0; mt < 4; mt++)
#pragma unroll
            for (int h = 0; h < 2; h++) {
                int row = mt*16 + q + 8*h;
#pragma unroll
                for (int cc = 0; cc < 3; cc++)
                    pd_sh[(w*64 + row)*3 + cc] = pdl[mt][h][cc];
            }
    }
    __syncthreads();
    if (tid < 192) {
        int row = tid / 3, cc = tid - row*3;
        float s = 0.f;
#pragma unroll
        for (int ww = 0; ww < 8; ww++) s += pd_sh[(ww*64 + row)*3 + cc];
        g_Pd[(size_t)(base + row)*3 + cc] = 0.25f*s + __ldg(pb2 + cc);
    }
}

// ---------------------------------------------------------------------------
// Final v3: smem-transposed GRU weights (conflict-free), 8 agents/block.
#define WSTR 193
__global__ void __launch_bounds__(512) final_kernel(
    const float* __restrict__ own,
    const float* __restrict__ fc1_w, const float* __restrict__ fc1_b,
    const float* __restrict__ merger_w,
    const float* __restrict__ hstate,
    const float* __restrict__ wih, const float* __restrict__ whh,
    const float* __restrict__ bih, const float* __restrict__ bhh,
    const float* __restrict__ fc2_w1, const float* __restrict__ fc2_b1,
    const float* __restrict__ fc2_w2, const float* __restrict__ fc2_b2,
    float* __restrict__ out_q, float* __restrict__ out_h) {
    extern __shared__ float dyn[];                 // wtih[64][193], wthh[64][193]
    float* wtih = dyn;
    float* wthh = dyn + 64*WSTR;
    __shared__ float own_sh[8][32], x_sh[8][64], h_sh[8][64], hh_sh[8][64], t_sh[8][64];
    const int tid = threadIdx.x;
    const int a = tid >> 6, j = tid & 63;
    const int r = blockIdx.x * 8 + a;

    // stage transposed GRU weights: coalesced gmem reads, conflict-free smem writes
    for (int idx = tid; idx < 192*64; idx += 512) {
        int g = idx >> 6, k = idx & 63;
        wtih[k*WSTR + g] = __ldg(wih + idx);
        wthh[k*WSTR + g] = __ldg(whh + idx);
    }
    if (j < 30) own_sh[a][j] = own[r*30 + j];
    h_sh[a][j] = hstate[r*64 + j];
    __syncthreads();

    float eo = fc1_b[j];
#pragma unroll
    for (int i = 0; i < 30; i += 2) {
        eo = fmaf(own_sh[a][i], __ldg(fc1_w + i*64 + j), eo);
        eo = fmaf(own_sh[a][i+1], __ldg(fc1_w + (i+1)*64 + j), eo);
    }
    float w0 = merger_w[j], w1v = merger_w[64+j], w2v = merger_w[128+j], w3v = merger_w[192+j];
    float mx = fmaxf(fmaxf(w0, w1v), fmaxf(w2v, w3v));
    float e0 = expf(w0-mx), e1 = expf(w1v-mx), e2 = expf(w2v-mx), e3 = expf(w3v-mx);
    float inv = 1.f / (e0+e1+e2+e3);
    const float* en = g_EmbEn + r*OD;
    const float* al = g_EmbAlSum + r*OD;
    float m = e0*inv*(en[j] + al[j]) + e1*inv*(en[64+j] + al[64+j])
            + e2*inv*(en[128+j] + al[128+j]) + e3*inv*(en[192+j] + al[192+j]);
    x_sh[a][j] = fmaxf(eo + m, 0.f);
    __syncthreads();

    // GRU: 6 independent accumulator chains, conflict-free LDS reads
    float gi0 = bih[j], gi1 = bih[64+j], gi2 = bih[128+j];
    float gh0 = bhh[j], gh1 = bhh[64+j], gh2 = bhh[128+j];
#pragma unroll 8
    for (int k = 0; k < 64; k++) {
        float xv = x_sh[a][k], hv = h_sh[a][k];
        const float* wi = wtih + k*WSTR;
        const float* wh = wthh + k*WSTR;
        gi0 = fmaf(xv, wi[j],       gi0);
        gi1 = fmaf(xv, wi[64 + j],  gi1);
        gi2 = fmaf(xv, wi[128 + j], gi2);
        gh0 = fmaf(hv, wh[j],       gh0);
        gh1 = fmaf(hv, wh[64 + j],  gh1);
        gh2 = fmaf(hv, wh[128 + j], gh2);
    }
    float rg = 1.f/(1.f + expf(-(gi0+gh0)));
    float zg = 1.f/(1.f + expf(-(gi1+gh1)));
    float ng = tanhf(gi2 + rg*gh2);
    float hh = (1.f - zg)*ng + zg*h_sh[a][j];
    hh_sh[a][j] = hh;
    out_h[r*64 + j] = hh;
    __syncthreads();

    float tt0 = fc2_b1[j], tt1 = 0.f;
#pragma unroll
    for (int k = 0; k < 64; k += 2) {
        tt0 = fmaf(hh_sh[a][k],   __ldg(fc2_w1 + k*64 + j),     tt0);
        tt1 = fmaf(hh_sh[a][k+1], __ldg(fc2_w1 + (k+1)*64 + j), tt1);
    }
    t_sh[a][j] = fmaxf(tt0 + tt1, 0.f);
    __syncthreads();

    if (j < 19) {
        float q0 = fc2_b2[j], q1 = 0.f;
#pragma unroll
        for (int mm = 0; mm < 64; mm += 2) {
            q0 = fmaf(t_sh[a][mm],   __ldg(fc2_w2 + mm*19 + j),     q0);
            q1 = fmaf(t_sh[a][mm+1], __ldg(fc2_w2 + (mm+1)*19 + j), q1);
        }
        int col = (j < 9) ? j : j + 3;
        out_q[r*22 + col] = q0 + q1;
    }
    if (j < 3) {
        float mxp = -INFINITY;
        for (int q = 0; q < NALLY; q++)
            mxp = fmaxf(mxp, g_Pd[(size_t)(r*NALLY + q)*3 + j]);
        out_q[r*22 + 9 + j] = mxp;
    }
}

extern "C" void kernel_launch(void* const* d_in, const int* in_sizes, int n_in,
                              void* d_out, int out_size) {
    const float* own    = (const float*)d_in[1];
    const float* ally   = (const float*)d_in[2];
    const float* enemy  = (const float*)d_in[3];
    const float* hstate = (const float*)d_in[4];
    const float* fc1_w  = (const float*)d_in[5];
    const float* fc1_b  = (const float*)d_in[6];
    const float* he_w1  = (const float*)d_in[7];
    const float* he_b1  = (const float*)d_in[8];
    const float* he_w2  = (const float*)d_in[9];
    const float* he_b2  = (const float*)d_in[10];
    const float* ha_w1  = (const float*)d_in[11];
    const float* ha_b1  = (const float*)d_in[12];
    const float* ha_w2  = (const float*)d_in[13];
    const float* ha_b2  = (const float*)d_in[14];
    const float* merger = (const float*)d_in[15];
    const float* wih    = (const float*)d_in[16];
    const float* whh    = (const float*)d_in[17];
    const float* bih    = (const float*)d_in[18];
    const float* bhh    = (const float*)d_in[19];
    const float* fc2_w1 = (const float*)d_in[20];
    const float* fc2_b1 = (const float*)d_in[21];
    const float* fc2_w2 = (const float*)d_in[22];
    const float* fc2_b2 = (const float*)d_in[23];
    const float* pw1    = (const float*)d_in[24];
    const float* pb1    = (const float*)d_in[25];
    const float* pw2    = (const float*)d_in[26];
    const float* pb2    = (const float*)d_in[27];

    float* out   = (float*)d_out;
    float* out_q = out;              // [2048, 22]
    float* out_h = out + RR*22;      // [2048, 64]

    const int fin_smem = 2*64*WSTR*sizeof(float);   // 98816 B
    static int once = 0;
    if (!once) {
        cudaFuncSetAttribute(final_kernel, cudaFuncAttributeMaxDynamicSharedMemorySize, fin_smem);
        once = 1;
    }

    wfrag_kernel<<<3*44, 256>>>(he_w2, he_b2, ha_w2, ha_b2, pw1);
    gemm_sum_kernel<<<128, 256>>>(enemy, ally, he_w1, he_b1, ha_w1, ha_b1);
    ally_mma_kernel<<<480, 256>>>(ally, ha_w1, ha_b1, pb1, pw2, pb2);
    final_kernel<<<RR/8, 512, fin_smem>>>(own, fc1_w, fc1_b, merger, hstate,
                                          wih, whh, bih, bhh,
                                          fc2_w1, fc2_b1, fc2_w2, fc2_b2,
                                          out_q, out_h);
}